// round 1
// baseline (speedup 1.0000x reference)
#include <cuda_runtime.h>
#include <math.h>

// ============================================================================
// ShapeRetrieval: fused cosine-sim top-1 retrieval.
//   q = normalize(Q) [N,D], g = normalize(G) [M,D]
//   sim = q @ g^T ; idx = argmax_m sim ; max_sim = max_m sim ; retrieved = table[idx]
// Output layout assumed: float32 [ idx(N) | max_sim(N) | retrieved(N) ]
//
// Strategy (Round 1, fp32 correctness baseline):
//   - per-row inverse norms precomputed (normalization folded into epilogue)
//   - tiled fp32 GEMM (128q x 64g x 32k), 256 threads, 8x4 micro-tile
//   - fused running (max, idx) per query row; cross-CTA merge via packed-u64
//     atomicMax (ordered-float key | ~idx  -> ties prefer smaller index,
//     matching jnp.argmax first-occurrence semantics)
// ============================================================================

#define TM 128          // query rows per CTA tile
#define TN 64           // gallery rows per CTA tile
#define TK 32           // k-chunk
#define NTHREADS 256
#define GSPLIT 37       // gallery strips -> 16 q-tiles * 37 = 592 CTAs (~2 waves @2/SM)

// Scratch (no cudaMalloc allowed): sized for this problem's fixed shapes.
__device__ unsigned long long d_best[4096];
__device__ float d_qinv[4096];
__device__ float d_ginv[100352];

// float -> monotonic unsigned key; idx stored complemented so that on equal
// sims the LARGER packed value corresponds to the SMALLER index.
__device__ __forceinline__ unsigned long long packKey(float v, int idx) {
    unsigned int b = __float_as_uint(v);
    b = (b & 0x80000000u) ? ~b : (b | 0x80000000u);
    return ((unsigned long long)b << 32) |
           (unsigned long long)(0xFFFFFFFFu - (unsigned int)idx);
}

__global__ void init_best(int n) {
    int i = blockIdx.x * blockDim.x + threadIdx.x;
    if (i < n) d_best[i] = 0ull;   // key 0 is unreachable by any finite float
}

// One warp per row: inv_norm = 1 / max(sqrt(sum x^2), 1e-12)
__global__ void row_inv_norm(const float* __restrict__ x, int rows, int D, int which) {
    int row = blockIdx.x * (blockDim.x >> 5) + (threadIdx.x >> 5);
    if (row >= rows) return;
    int lane = threadIdx.x & 31;
    const float4* p = (const float4*)(x + (size_t)row * D);
    float s = 0.f;
    for (int i = lane; i < (D >> 2); i += 32) {
        float4 v = p[i];
        s += v.x * v.x + v.y * v.y + v.z * v.z + v.w * v.w;
    }
    #pragma unroll
    for (int o = 16; o; o >>= 1) s += __shfl_xor_sync(0xFFFFFFFFu, s, o);
    if (lane == 0) {
        float inv = 1.0f / fmaxf(sqrtf(s), 1e-12f);
        if (which == 0) d_qinv[row] = inv;
        else            d_ginv[row] = inv;
    }
}

__global__ __launch_bounds__(NTHREADS, 2)
void sim_argmax(const float* __restrict__ Q, const float* __restrict__ G,
                int N, int M, int D) {
    __shared__ union {
        struct {
            float As[TK][TM + 4];   // k-major, 16B-aligned rows (132*4 = 528 B)
            float Bs[TK][TN + 4];   // 68*4 = 272 B rows
        } t;
        unsigned long long red[TM][16];
    } sm;

    const int tid = threadIdx.x;
    const int tx = tid & 15;      // gallery-col group (16)
    const int ty = tid >> 4;      // query-row group (16)
    const int qbase = blockIdx.y * TM;

    float rmax[8];
    int   ridx[8];
    #pragma unroll
    for (int i = 0; i < 8; i++) { rmax[i] = -1e30f; ridx[i] = 0; }

    const int numTiles = (M + TN - 1) / TN;
    for (int t = blockIdx.x; t < numTiles; t += GSPLIT) {
        const int gbase = t * TN;

        float acc[8][4];
        #pragma unroll
        for (int i = 0; i < 8; i++)
            #pragma unroll
            for (int j = 0; j < 4; j++) acc[i][j] = 0.f;

        for (int kc = 0; kc < D; kc += TK) {
            // ---- load A tile (128 x 32) transposed into smem ----
            {
                const int c4 = tid & 7;     // float4 slot within 32-col chunk
                const int r0 = tid >> 3;    // 0..31
                #pragma unroll
                for (int s = 0; s < 4; s++) {
                    int r = r0 + 32 * s;
                    int row = qbase + r;
                    float4 v = make_float4(0.f, 0.f, 0.f, 0.f);
                    if (row < N)
                        v = *(const float4*)(Q + (size_t)row * D + kc + c4 * 4);
                    sm.t.As[c4 * 4 + 0][r] = v.x;
                    sm.t.As[c4 * 4 + 1][r] = v.y;
                    sm.t.As[c4 * 4 + 2][r] = v.z;
                    sm.t.As[c4 * 4 + 3][r] = v.w;
                }
                // ---- load B tile (64 x 32) transposed ----
                #pragma unroll
                for (int s = 0; s < 2; s++) {
                    int r = r0 + 32 * s;
                    int row = gbase + r;
                    float4 v = make_float4(0.f, 0.f, 0.f, 0.f);
                    if (row < M)
                        v = *(const float4*)(G + (size_t)row * D + kc + c4 * 4);
                    sm.t.Bs[c4 * 4 + 0][r] = v.x;
                    sm.t.Bs[c4 * 4 + 1][r] = v.y;
                    sm.t.Bs[c4 * 4 + 2][r] = v.z;
                    sm.t.Bs[c4 * 4 + 3][r] = v.w;
                }
            }
            __syncthreads();

            #pragma unroll
            for (int k = 0; k < TK; k++) {
                float4 a0 = *(const float4*)&sm.t.As[k][ty * 8];
                float4 a1 = *(const float4*)&sm.t.As[k][ty * 8 + 4];
                float4 b0 = *(const float4*)&sm.t.Bs[k][tx * 4];
                float a[8] = {a0.x, a0.y, a0.z, a0.w, a1.x, a1.y, a1.z, a1.w};
                float b[4] = {b0.x, b0.y, b0.z, b0.w};
                #pragma unroll
                for (int i = 0; i < 8; i++)
                    #pragma unroll
                    for (int j = 0; j < 4; j++)
                        acc[i][j] = fmaf(a[i], b[j], acc[i][j]);
            }
            __syncthreads();
        }

        // ---- epilogue: scale by gallery inv-norm, update running (max, idx) ----
        float gv[4]; int cv[4];
        #pragma unroll
        for (int j = 0; j < 4; j++) {
            int c = gbase + tx * 4 + j;
            cv[j] = c;
            gv[j] = (c < M) ? d_ginv[c] : 0.f;
        }
        #pragma unroll
        for (int i = 0; i < 8; i++) {
            #pragma unroll
            for (int j = 0; j < 4; j++) {
                if (cv[j] < M) {
                    float v = acc[i][j] * gv[j];
                    if (v > rmax[i] || (v == rmax[i] && cv[j] < ridx[i])) {
                        rmax[i] = v; ridx[i] = cv[j];
                    }
                }
            }
        }
    }

    // ---- cross-thread reduce (16 tx lanes share each query row) + global merge ----
    __syncthreads();   // before smem union reuse
    #pragma unroll
    for (int i = 0; i < 8; i++) {
        int row = ty * 8 + i;
        int qrow = qbase + row;
        float qi = (qrow < N) ? d_qinv[qrow] : 0.f;   // qi > 0: order-preserving
        sm.red[row][tx] = packKey(rmax[i] * qi, ridx[i]);
    }
    __syncthreads();
    if (tid < TM) {
        unsigned long long best = sm.red[tid][0];
        #pragma unroll
        for (int j = 1; j < 16; j++) {
            unsigned long long v = sm.red[tid][j];
            if (v > best) best = v;
        }
        int qrow = qbase + tid;
        if (qrow < N) atomicMax(&d_best[qrow], best);
    }
}

__global__ void finalize(const int* __restrict__ table, float* __restrict__ out,
                         int N, int out_size) {
    int i = blockIdx.x * blockDim.x + threadIdx.x;
    if (i >= N) return;
    unsigned long long p = d_best[i];
    unsigned int kb = (unsigned int)(p >> 32);
    unsigned int ob = (kb & 0x80000000u) ? (kb ^ 0x80000000u) : ~kb;
    float v = __uint_as_float(ob);
    int idx = (int)(0xFFFFFFFFu - (unsigned int)(p & 0xFFFFFFFFu));
    if (i < out_size)         out[i]         = (float)idx;
    if (N + i < out_size)     out[N + i]     = v;
    if (2 * N + i < out_size) out[2 * N + i] = (float)table[idx];
}

extern "C" void kernel_launch(void* const* d_in, const int* in_sizes, int n_in,
                              void* d_out, int out_size) {
    const float* Q     = (const float*)d_in[0];
    const float* G     = (const float*)d_in[1];
    const int*   table = (const int*)d_in[2];

    const int M = in_sizes[2];             // 100000
    const int D = in_sizes[1] / M;         // 256
    const int N = in_sizes[0] / D;         // 2048
    float* out = (float*)d_out;

    init_best<<<(N + 255) / 256, 256>>>(N);
    row_inv_norm<<<(N + 7) / 8, 256>>>(Q, N, D, 0);
    row_inv_norm<<<(M + 7) / 8, 256>>>(G, M, D, 1);

    dim3 grid(GSPLIT, (N + TM - 1) / TM);
    sim_argmax<<<grid, NTHREADS>>>(Q, G, N, M, D);

    finalize<<<(N + 255) / 256, 256>>>(table, out, N, out_size);
}

// round 3
// speedup vs baseline: 3.0945x; 3.0945x over previous
#include <cuda_runtime.h>
#include <cuda_bf16.h>
#include <math.h>
#include <stdint.h>

// ============================================================================
// ShapeRetrieval: fused cosine-sim top-1 retrieval. Two-pass bf16 mma.sync
// (legacy HMMA, plain sm_100 target) + exact fp32 rescore.
//   Pass A: bf16 GEMM -> per-query approx max (running, per-CTA partials)
//   thr[q] = amaxA[q] - 0.02   (sound: bf16 sim error <= ~1.6e-2 total margin)
//   Pass B: same GEMM -> push (q,m) with sim_bf16 >= thr[q]  (~3/query)
//   Rescore: exact fp32 warp-dot -> packed u64 atomicMax (ties: smaller idx)
// Output: float32 [ idx(N) | max_sim(N) | retrieved(N) ]
// ============================================================================

#define NQ     2048
#define MG     100000
#define DK     256
#define GTILES 782                // ceil(100000/128)
#define MPAD   (GTILES * 128)     // 100096
#define GRID   148
#define NQT    16                 // 2048/128
#define CAP    262144
#define MARG   0.02f

// smem tile geometry: 128 rows x 256 bf16, row stride 264 halves (528 B)
#define RSB        528
#define TILE_BYTES (128 * RSB)    // 67584
#define QOFF0      0
#define QOFF1      TILE_BYTES
#define GOFF       (2 * TILE_BYTES)
#define RUNOFF     (3 * TILE_BYTES)          // unsigned[2048] = 8 KB
#define SMEM_BYTES (RUNOFF + NQ * 4)         // 210944

// ---------------- device globals (no cudaMalloc allowed) --------------------
__device__ __nv_bfloat16 g_Qb[NQ * DK];
__device__ __nv_bfloat16 g_Gb[(size_t)MPAD * DK];
__device__ float g_qinv[NQ];
__device__ float g_ginv[MPAD];
__device__ unsigned int g_partA[GRID * NQ];
__device__ float g_thr[NQ];
__device__ unsigned long long g_best[NQ];
__device__ unsigned int g_cand[CAP];
__device__ unsigned int g_ccnt;

// ---------------- helpers ---------------------------------------------------
__device__ __forceinline__ uint32_t smem_u32(const void* p) {
    uint32_t a;
    asm("{ .reg .u64 t; cvta.to.shared.u64 t, %1; cvt.u32.u64 %0, t; }"
        : "=r"(a) : "l"(p));
    return a;
}

__device__ __forceinline__ void cpa16(uint32_t dst, const void* src) {
    asm volatile("cp.async.cg.shared.global [%0], [%1], 16;"
                 :: "r"(dst), "l"(src));
}
#define CPA_COMMIT() asm volatile("cp.async.commit_group;" ::: "memory")
#define CPA_WAIT0()  asm volatile("cp.async.wait_group 0;" ::: "memory")

__device__ __forceinline__ void ldmx4(uint32_t* r, uint32_t addr) {
    asm volatile("ldmatrix.sync.aligned.m8n8.x4.shared.b16 {%0,%1,%2,%3}, [%4];"
                 : "=r"(r[0]), "=r"(r[1]), "=r"(r[2]), "=r"(r[3]) : "r"(addr));
}

__device__ __forceinline__ void mma16816(float* c, const uint32_t* a,
                                         const uint32_t* b) {
    asm volatile(
        "mma.sync.aligned.m16n8k16.row.col.f32.bf16.bf16.f32 "
        "{%0,%1,%2,%3}, {%4,%5,%6,%7}, {%8,%9}, {%0,%1,%2,%3};"
        : "+f"(c[0]), "+f"(c[1]), "+f"(c[2]), "+f"(c[3])
        : "r"(a[0]), "r"(a[1]), "r"(a[2]), "r"(a[3]), "r"(b[0]), "r"(b[1]));
}

// float -> monotonic uint (order-preserving incl. negatives)
__device__ __forceinline__ unsigned int flipU(float v) {
    unsigned int b = __float_as_uint(v);
    return (b & 0x80000000u) ? ~b : (b | 0x80000000u);
}
__device__ __forceinline__ float unflipU(unsigned int k) {
    return (k & 0x80000000u) ? __uint_as_float(k ^ 0x80000000u)
                             : __uint_as_float(~k);
}
__device__ __forceinline__ unsigned long long packKey(float v, int idx) {
    return ((unsigned long long)flipU(v) << 32) |
           (unsigned long long)(0xFFFFFFFFu - (unsigned int)idx);
}

// ---------------- small kernels ---------------------------------------------
__global__ void init_state() {
    int i = blockIdx.x * blockDim.x + threadIdx.x;
    if (i < NQ) g_best[i] = 0ull;
    if (i == 0) g_ccnt = 0u;
}

// normalize rows in fp32, write bf16; zero-pad rows >= validRows
__global__ void prep_rows(const float* __restrict__ src, int rows, int validRows,
                          __nv_bfloat16* __restrict__ dst, float* __restrict__ inv) {
    int row = blockIdx.x * (blockDim.x >> 5) + (threadIdx.x >> 5);
    if (row >= rows) return;
    int lane = threadIdx.x & 31;
    char* drow = (char*)(dst + (size_t)row * DK);
    if (row >= validRows) {
        *(uint4*)(drow + lane * 16) = make_uint4(0u, 0u, 0u, 0u);
        if (lane == 0) inv[row] = 0.f;
        return;
    }
    const float4* p = (const float4*)(src + (size_t)row * DK);
    float4 a = p[lane * 2], b = p[lane * 2 + 1];
    float s = a.x*a.x + a.y*a.y + a.z*a.z + a.w*a.w
            + b.x*b.x + b.y*b.y + b.z*b.z + b.w*b.w;
    #pragma unroll
    for (int o = 16; o; o >>= 1) s += __shfl_xor_sync(0xFFFFFFFFu, s, o);
    float iv = 1.0f / fmaxf(sqrtf(s), 1e-12f);
    if (lane == 0) inv[row] = iv;
    __nv_bfloat162 q0 = __floats2bfloat162_rn(a.x * iv, a.y * iv);
    __nv_bfloat162 q1 = __floats2bfloat162_rn(a.z * iv, a.w * iv);
    __nv_bfloat162 q2 = __floats2bfloat162_rn(b.x * iv, b.y * iv);
    __nv_bfloat162 q3 = __floats2bfloat162_rn(b.z * iv, b.w * iv);
    uint4 o4;
    o4.x = *(unsigned int*)&q0; o4.y = *(unsigned int*)&q1;
    o4.z = *(unsigned int*)&q2; o4.w = *(unsigned int*)&q3;
    *(uint4*)(drow + lane * 16) = o4;
}

__global__ void reduceA() {
    int q = blockIdx.x * blockDim.x + threadIdx.x;
    if (q >= NQ) return;
    unsigned int mx = 0u;
    for (int s = 0; s < GRID; s++) {
        unsigned int v = g_partA[s * NQ + q];
        if (v > mx) mx = v;
    }
    g_thr[q] = unflipU(mx) - MARG;
}

__global__ void rescore(const float* __restrict__ Q, const float* __restrict__ G) {
    unsigned cnt = g_ccnt; if (cnt > CAP) cnt = CAP;
    int wid = (blockIdx.x * blockDim.x + threadIdx.x) >> 5;
    int lane = threadIdx.x & 31;
    int nw = (gridDim.x * blockDim.x) >> 5;
    for (unsigned i = wid; i < cnt; i += nw) {
        unsigned e = g_cand[i];
        int q = (int)(e >> 17), m = (int)(e & 0x1FFFFu);
        const float4* qp = (const float4*)(Q + (size_t)q * DK);
        const float4* gp = (const float4*)(G + (size_t)m * DK);
        float s = 0.f;
        #pragma unroll
        for (int j = 0; j < 2; j++) {
            float4 a = qp[lane * 2 + j], b = gp[lane * 2 + j];
            s += a.x*b.x + a.y*b.y + a.z*b.z + a.w*b.w;
        }
        #pragma unroll
        for (int o = 16; o; o >>= 1) s += __shfl_xor_sync(0xFFFFFFFFu, s, o);
        if (lane == 0) {
            float v = s * g_qinv[q] * g_ginv[m];
            atomicMax(&g_best[q], packKey(v, m));
        }
    }
}

__global__ void finalize(const int* __restrict__ table, float* __restrict__ out,
                         int n, int out_size) {
    int i = blockIdx.x * blockDim.x + threadIdx.x;
    if (i >= n) return;
    unsigned long long p = g_best[i];
    int idx = 0; float v = 0.f;
    if (p != 0ull) {
        v = unflipU((unsigned int)(p >> 32));
        idx = (int)(0xFFFFFFFFu - (unsigned int)(p & 0xFFFFFFFFu));
        if (idx < 0 || idx >= MG) idx = 0;
    }
    if (i < out_size)         out[i]         = (float)idx;
    if (n + i < out_size)     out[n + i]     = v;
    if (2 * n + i < out_size) out[2 * n + i] = (float)table[idx];
}

// ---------------- main GEMM pass --------------------------------------------
// 148 CTAs x 256 thr. CTA owns gallery strips (stride GRID); G tile resident,
// Q tiles double-buffered. Warp grid 2(q) x 4(g); warp tile 64q x 32g.
__device__ __forceinline__ void load_tile(uint32_t sdst, const char* gsrc, int tid) {
    #pragma unroll
    for (int it = 0; it < 16; it++) {
        int li = tid + it * 256;
        int row = li >> 5, ch = li & 31;
        cpa16(sdst + row * RSB + ch * 16, gsrc + (size_t)row * 512 + ch * 16);
    }
}

__global__ void __launch_bounds__(256, 1) pass_kernel(int mode) {
    extern __shared__ __align__(16) char smraw[];
    const uint32_t sb = smem_u32(smraw);
    unsigned int* run = (unsigned int*)(smraw + RUNOFF);

    const int tid  = threadIdx.x;
    const int w    = tid >> 5;
    const int lane = tid & 31;

    if (mode == 0)
        for (int i = tid; i < NQ; i += 256) run[i] = 0u;
    __syncthreads();

    const int wq = w >> 2;             // 0..1  (query half)
    const int wg = w & 3;              // 0..3  (gallery quarter)
    const int m0 = wq * 64;
    const int n0 = wg * 32;
    const int gid = lane >> 2, tig = lane & 3;
    const int t8 = lane >> 3, lr = lane & 7;

    // ldmatrix per-lane base offsets (within a tile)
    const uint32_t aoff = (uint32_t)(m0 + (t8 & 1) * 8 + lr) * RSB + (t8 >> 1) * 16;
    const uint32_t boff = (uint32_t)(n0 + (t8 >> 1) * 8 + lr) * RSB + (t8 & 1) * 16;
    const uint32_t gsb  = sb + GOFF;

    for (int gt = blockIdx.x; gt < GTILES; gt += GRID) {
        const int gbase = gt * 128;

        load_tile(sb + GOFF, (const char*)g_Gb + (size_t)gbase * 512, tid);
        load_tile(sb + QOFF0, (const char*)g_Qb, tid);
        CPA_COMMIT();
        CPA_WAIT0();
        __syncthreads();

        for (int qt = 0; qt < NQT; qt++) {
            const int b = qt & 1;
            if (qt + 1 < NQT) {
                load_tile(sb + (b ? QOFF0 : QOFF1),
                          (const char*)g_Qb + (size_t)(qt + 1) * 128 * 512, tid);
                CPA_COMMIT();
            }

            // ---- compute 128x128 on (qs[b], gs) ----
            const uint32_t qsb = sb + (b ? QOFF1 : QOFF0);
            float c[4][16];
            #pragma unroll
            for (int mt = 0; mt < 4; mt++)
                #pragma unroll
                for (int j = 0; j < 16; j++) c[mt][j] = 0.f;

            #pragma unroll
            for (int ks = 0; ks < 16; ks++) {
                const uint32_t ka = (uint32_t)ks * 32;
                uint32_t a[4][4], bb[2][4];
                #pragma unroll
                for (int mt = 0; mt < 4; mt++)
                    ldmx4(a[mt], qsb + aoff + (uint32_t)mt * (16 * RSB) + ka);
                #pragma unroll
                for (int np = 0; np < 2; np++)
                    ldmx4(bb[np], gsb + boff + (uint32_t)np * (16 * RSB) + ka);
                #pragma unroll
                for (int mt = 0; mt < 4; mt++) {
                    #pragma unroll
                    for (int nt = 0; nt < 4; nt++)
                        mma16816(&c[mt][nt * 4], a[mt], &bb[nt >> 1][(nt & 1) * 2]);
                }
            }

            // ---- epilogue ----
            if (mode == 0) {
                #pragma unroll
                for (int mt = 0; mt < 4; mt++) {
                    float v0 = -1e30f, v1 = -1e30f;
                    #pragma unroll
                    for (int nt = 0; nt < 4; nt++) {
                        v0 = fmaxf(v0, fmaxf(c[mt][nt*4+0], c[mt][nt*4+1]));
                        v1 = fmaxf(v1, fmaxf(c[mt][nt*4+2], c[mt][nt*4+3]));
                    }
                    v0 = fmaxf(v0, __shfl_xor_sync(0xFFFFFFFFu, v0, 1));
                    v0 = fmaxf(v0, __shfl_xor_sync(0xFFFFFFFFu, v0, 2));
                    v1 = fmaxf(v1, __shfl_xor_sync(0xFFFFFFFFu, v1, 1));
                    v1 = fmaxf(v1, __shfl_xor_sync(0xFFFFFFFFu, v1, 2));
                    if (tig == 0) {
                        int r0 = qt * 128 + m0 + mt * 16 + gid;
                        atomicMax(&run[r0],     flipU(v0));
                        atomicMax(&run[r0 + 8], flipU(v1));
                    }
                }
            } else {
                #pragma unroll
                for (int mt = 0; mt < 4; mt++) {
                    const int q0 = qt * 128 + m0 + mt * 16 + gid;
                    const float th0 = g_thr[q0];
                    const float th1 = g_thr[q0 + 8];
                    #pragma unroll
                    for (int nt = 0; nt < 4; nt++) {
                        const int col = gbase + n0 + nt * 8 + 2 * tig;
                        #pragma unroll
                        for (int e = 0; e < 4; e++) {
                            const float v = c[mt][nt * 4 + e];
                            const int qq = (e >= 2) ? q0 + 8 : q0;
                            const float th = (e >= 2) ? th1 : th0;
                            const int mm = col + (e & 1);
                            if (v >= th && mm < MG) {
                                unsigned pos = atomicAdd(&g_ccnt, 1u);
                                if (pos < CAP)
                                    g_cand[pos] = ((unsigned)qq << 17) | (unsigned)mm;
                            }
                        }
                    }
                }
            }

            CPA_WAIT0();
            __syncthreads();
        }
    }

    if (mode == 0) {
        __syncthreads();
        for (int i = tid; i < NQ; i += 256)
            g_partA[blockIdx.x * NQ + i] = run[i];
    }
}

// ---------------- launch ----------------------------------------------------
extern "C" void kernel_launch(void* const* d_in, const int* in_sizes, int n_in,
                              void* d_out, int out_size) {
    const float* Q     = (const float*)d_in[0];
    const float* G     = (const float*)d_in[1];
    const int*   table = (const int*)d_in[2];
    float* out = (float*)d_out;

    static int attr_done = 0;
    if (!attr_done) {
        cudaFuncSetAttribute(pass_kernel,
                             cudaFuncAttributeMaxDynamicSharedMemorySize, SMEM_BYTES);
        attr_done = 1;
    }

    __nv_bfloat16 *qb = nullptr, *gb = nullptr;
    float *qi = nullptr, *gi = nullptr;
    cudaGetSymbolAddress((void**)&qb, g_Qb);
    cudaGetSymbolAddress((void**)&gb, g_Gb);
    cudaGetSymbolAddress((void**)&qi, g_qinv);
    cudaGetSymbolAddress((void**)&gi, g_ginv);

    init_state<<<(NQ + 255) / 256, 256>>>();
    prep_rows<<<NQ / 8, 256>>>(Q, NQ, NQ, qb, qi);
    prep_rows<<<MPAD / 8, 256>>>(G, MPAD, MG, gb, gi);

    pass_kernel<<<GRID, 256, SMEM_BYTES>>>(0);
    reduceA<<<(NQ + 255) / 256, 256>>>();
    pass_kernel<<<GRID, 256, SMEM_BYTES>>>(1);

    rescore<<<256, 256>>>(Q, G);
    finalize<<<(NQ + 255) / 256, 256>>>(table, out, NQ, out_size);
}